// round 11
// baseline (speedup 1.0000x reference)
#include <cuda_runtime.h>

// DistanceTransformMap: exact EDT + approx-sqrt (rel err ~2^-23 << 1e-3),
// SINGLE kernel. Each block = (batch, 8-column strip):
//   1) ballot-compress the 3 bitmap word-slabs it needs, straight from mask
//      (redundant across blocks -> no inter-block dependency, no 2nd launch);
//   2) row distances via 64-bit funnel bit-scans (exact; empty-window
//      fallback scans the mask row directly in global -> exact for any input;
//      out-of-range words are zero -> boundary-exact; no zero in row ->
//      d >= 384 -> LARGE, matching reference);
//   3) column expanding search: near window d<=4 unconditional (extra
//      candidates are upper bounds); far case (best>25) clamped onto LARGE
//      pads (left 0..7, right 392..399) -> never wins -> exact.
// All EDT intermediates are exact integers < 2^24 in fp32.

constexpr int Bn = 4;
constexpr int Hn = 384;
constexpr int Wn = 384;
constexpr int N  = 384;
constexpr float LARGE = 2.0f * (float)(Hn * Hn + Wn * Wn);  // 589824 > 383^2

constexpr int PAD = 8;
constexpr int LWD = N + 2 * PAD;              // 400
constexpr int LWP = 403;                      // padded line stride (odd)
constexpr int CPB = 8;                        // columns per block
constexpr int NT  = 768;                      // 24 warps
constexpr int NSTRIP = Wn / CPB;              // 48

__device__ __forceinline__ float sqrt_approx(float x) {
    float r;
    asm("sqrt.approx.f32 %0, %1;" : "=f"(r) : "f"(x));
    return r;
}

__device__ __forceinline__ float near_far(const float* __restrict__ row,
                                          float best, int i) {
    if (best > 25.0f) {                        // rare exact continuation
        float df = 5.0f;
        int d = 5;
        const int ip = i + PAD;
        while (df * df < best && d < N) {
#pragma unroll
            for (int u = 0; u < 4; ++u) {
                const int jr = min(ip + d + u, LWD - 1);
                const int jl = max(ip - d - u, 0);
                const float e = df + (float)u;
                best = fminf(best, fmaf(e, e, fminf(row[jr], row[jl])));
            }
            df += 4.0f;
            d += 4;
        }
    }
    return best;
}

__global__ __launch_bounds__(NT, 2) void edt_fused(const float* __restrict__ mask,
                                                   float* __restrict__ out) {
    __shared__ unsigned sh_t[3 * Hn];          // word-slabs jw-1..jw+1, [q][y]
    __shared__ float lines[CPB * LWP];         // padded column-lines
    __shared__ float sh_o[Hn * 9];             // output stage [y][c], stride 9

    const int t = threadIdx.x;
    const int w = t >> 5, lane = t & 31;
    const int b = blockIdx.x / NSTRIP;
    const int x0 = (blockIdx.x - b * NSTRIP) * CPB;
    const int jw = x0 >> 5;                    // word of x0; bp0 = x0&31 <= 24
    const float* __restrict__ mb = mask + (size_t)b * Hn * Wn;

    // ---- 1. Ballot-compress the 3 needed word-slabs from mask ----
#pragma unroll
    for (int q = 0; q < 3; ++q) {
        const int j = jw - 1 + q;
        const bool inr = (j >= 0) && (j < 12);
        const float* __restrict__ src = mb + j * 32 + lane;
#pragma unroll 8
        for (int iy = 0; iy < 16; ++iy) {
            const int y = w + 24 * iy;
            const float v = inr ? src[(size_t)y * Wn] : 1.0f;  // coalesced 128B
            const unsigned m = __ballot_sync(0xffffffffu, v <= 0.5f);
            if (lane == 0) sh_t[q * Hn + y] = m;
        }
    }
    if (t < CPB * PAD) {                       // LARGE pads for column lines
        const int c = t >> 3, o = t & 7;
        lines[c * LWP + o] = LARGE;
        lines[c * LWP + LWD - PAD + o] = LARGE;
    }
    __syncthreads();

    // ---- 2. Row distances: 2 threads per y, 4 funnel scans each ----
    {
        const int y = t >> 1, half = t & 1;
        const unsigned wm1 = sh_t[y];
        const unsigned w0  = sh_t[Hn + y];
        const unsigned wp1 = sh_t[2 * Hn + y];
        const unsigned long long vr = ((unsigned long long)wp1 << 32) | w0;
        const unsigned long long vl = ((unsigned long long)w0 << 32) | wm1;
        const int bp0 = (x0 & 31) + half * 4;
        const float* __restrict__ mrow = mb + (size_t)y * Wn;
#pragma unroll
        for (int u = 0; u < 4; ++u) {
            const int bp = bp0 + u;            // <= 31
            const int xl = half * 4 + u;
            const int xg = x0 + xl;
            int dr, dl;
            const unsigned long long r64 = vr >> bp;
            if (r64) {
                dr = __ffsll(r64) - 1;
            } else {                            // rare exact fallback: scan mask
                dr = 0x7fff;
                for (int xx = (jw + 2) * 32; xx < N; ++xx)
                    if (mrow[xx] <= 0.5f) { dr = xx - xg; break; }
            }
            const unsigned long long l64 = vl << (31 - bp);
            if (l64) {
                dl = __clzll(l64);
            } else {
                dl = 0x7fff;
                for (int xx = (jw - 1) * 32 - 1; xx >= 0; --xx)
                    if (mrow[xx] <= 0.5f) { dl = xg - xx; break; }
            }
            const int d = min(dl, dr);
            lines[xl * LWP + PAD + y] = (d < 384) ? (float)(d * d) : LARGE;
        }
    }
    __syncthreads();

    // ---- 3. Column search: 24 warps = 3 segments x 8 columns ----
    const int cl = w & 7, seg = w >> 3;
    const float* __restrict__ row = &lines[cl * LWP];
    const int ibase = seg * 128 + lane;

    float best[4];
#pragma unroll
    for (int gq = 0; gq < 4; gq += 2) {        // groups of 2 searches (18 LDS MLP)
        float a[2][9];
#pragma unroll
        for (int s = 0; s < 2; ++s) {
            const float* p = row + PAD + ibase + 32 * (gq + s);
            a[s][0] = p[0];
            a[s][1] = p[1];  a[s][2] = p[-1];
            a[s][3] = p[2];  a[s][4] = p[-2];
            a[s][5] = p[3];  a[s][6] = p[-3];
            a[s][7] = p[4];  a[s][8] = p[-4];
        }
#pragma unroll
        for (int s = 0; s < 2; ++s) {
            const float c1 = fminf(a[s][1], a[s][2]) + 1.0f;
            const float c2 = fminf(a[s][3], a[s][4]) + 4.0f;
            const float c3 = fminf(a[s][5], a[s][6]) + 9.0f;
            const float c4 = fminf(a[s][7], a[s][8]) + 16.0f;
            best[gq + s] = fminf(a[s][0], fminf(fminf(c1, c2), fminf(c3, c4)));
        }
    }
#pragma unroll
    for (int s = 0; s < 4; ++s)
        best[s] = near_far(row, best[s], ibase + 32 * s);

#pragma unroll
    for (int s = 0; s < 4; ++s)
        sh_o[(ibase + 32 * s) * 9 + cl] = sqrt_approx(best[s]);
    __syncthreads();

    // ---- 4. Tile store: 8 consecutive floats per y ----
    const int c_st = t & 7, y_st = t >> 3;     // y_st in 0..95
    float* __restrict__ dst = out + (size_t)b * Hn * Wn + x0 + c_st;
#pragma unroll
    for (int r = 0; r < 4; ++r) {
        const int y = y_st + 96 * r;
        dst[(size_t)y * Wn] = sh_o[y * 9 + c_st];
    }
}

extern "C" void kernel_launch(void* const* d_in, const int* in_sizes, int n_in,
                              void* d_out, int out_size) {
    const float* mask = (const float*)d_in[0];
    float* out = (float*)d_out;
    (void)in_sizes; (void)n_in; (void)out_size;

    edt_fused<<<Bn * NSTRIP, NT>>>(mask, out);
}

// round 12
// speedup vs baseline: 1.2179x; 1.2179x over previous
#include <cuda_runtime.h>

// DistanceTransformMap: exact EDT + approx-sqrt (rel err ~2^-23 << 1e-3).
// SINGLE kernel, two phases split by one grid barrier:
//  Phase 1: non-redundant ballot-compress of the zero-pixel bitmap into
//           TRANSPOSED g_bm_t[b][word+1][y] (+ zero word-pads). Each block
//           owns 4 rows; each of its 12 warps does 4 LDG + 4 ballots.
//  Phase 2: per-(batch, 4-column strip): load the 3 needed word-slabs
//           (contiguous, L2-hot), row distances via 64-bit funnel bit-scans,
//           then the proven column expanding search (R10).
//
// Barrier: monotonic counter (never reset) -> correct across CUDA-graph
// replays (stream order serializes calls). grid=384 blocks at occ>=3 on
// 148 SMs -> all blocks wave-1 resident -> deadlock-free.
//
// Exactness of the EDT (before sqrt):
//  - funnel covers >=33 bits each direction; empty window -> exact global
//    word loop; zero word-pads make boundaries exact; no zero in row ->
//    d >= 384 -> LARGE (matches reference: min attained at j=i is LARGE).
//  - column near window d<=4 unconditional: extra candidates = upper bounds.
//  - far case (best>25): clamped indices land on LARGE pads (left 0..7,
//    right 392..399); LARGE + d^2 > LARGE >= best0 never wins.
// All EDT intermediates are exact integers < 2^24 in fp32.

constexpr int Bn = 4;
constexpr int Hn = 384;
constexpr int Wn = 384;
constexpr int N  = 384;
constexpr int JW = 14;                        // 12 words + 2 zero pads
constexpr float LARGE = 2.0f * (float)(Hn * Hn + Wn * Wn);  // 589824 > 383^2

constexpr int PAD = 8;
constexpr int LWD = N + 2 * PAD;              // 400
constexpr int LWP = 403;                      // padded line stride
constexpr int CPB = 4;                        // columns per block (phase 2)
constexpr int NT  = 384;
constexpr int GRID = Bn * (Wn / CPB);         // 384

__device__ unsigned g_bm_t[Bn * JW * Hn];     // transposed bitmap
__device__ unsigned g_bar;                    // monotonic barrier counter

__device__ __forceinline__ float sqrt_approx(float x) {
    float r;
    asm("sqrt.approx.f32 %0, %1;" : "=f"(r) : "f"(x));
    return r;
}

__device__ __forceinline__ float near_far(const float* __restrict__ row,
                                          float best, int i) {
    if (best > 25.0f) {                        // rare exact continuation
        float df = 5.0f;
        int d = 5;
        const int ip = i + PAD;
        while (df * df < best && d < N) {
#pragma unroll
            for (int u = 0; u < 4; ++u) {
                const int jr = min(ip + d + u, LWD - 1);
                const int jl = max(ip - d - u, 0);
                const float e = df + (float)u;
                best = fminf(best, fmaf(e, e, fminf(row[jr], row[jl])));
            }
            df += 4.0f;
            d += 4;
        }
    }
    return best;
}

__device__ __forceinline__ void grid_barrier() {
    __threadfence();                           // publish my stores (all threads)
    __syncthreads();
    if (threadIdx.x == 0) {
        const unsigned old = atomicAdd(&g_bar, 1u);
        const unsigned target = old - (old % GRID) + GRID;
        while (atomicAdd(&g_bar, 0u) < target) {
            __nanosleep(64);
        }
        __threadfence();                       // acquire
    }
    __syncthreads();
}

__global__ __launch_bounds__(NT, 3) void edt_all(const float* __restrict__ mask,
                                                 float* __restrict__ out) {
    __shared__ unsigned sh_t[3 * Hn];          // 3 word-slabs [q][y]
    __shared__ float lines[CPB * LWP];
    __shared__ float sh_o[Hn * 5];             // output stage [y][c]

    const int t = threadIdx.x;
    const int w = t >> 5, lane = t & 31;

    // ---- Phase 1: compress 4 rows per block (non-redundant) ----
    {
        const int row_k = w & 3;               // which of my block's 4 rows
        const int grp = w >> 2;                // word group 0..2 (words 4g..4g+3)
        const int L = blockIdx.x * 4 + row_k;  // global row 0..1535
        const int b = L / Hn, y = L - b * Hn;
        unsigned* __restrict__ dstb = g_bm_t + (size_t)b * JW * Hn;
        const float* __restrict__ srow = mask + (size_t)L * N;
#pragma unroll
        for (int u = 0; u < 4; ++u) {
            const int j = grp * 4 + u;
            const float v = srow[j * 32 + lane];              // coalesced 128B
            const unsigned m = __ballot_sync(0xffffffffu, v <= 0.5f);
            if (lane == j) dstb[(j + 1) * Hn + y] = m;
        }
        if (grp == 0) {                        // zero word-pads for this row
            if (lane == 12) dstb[y] = 0u;
            if (lane == 13) dstb[13 * Hn + y] = 0u;
        }
    }

    grid_barrier();                            // whole bitmap visible

    // ---- Phase 2: proven R10 main ----
    const int b = blockIdx.x / (Wn / CPB);
    const int x0 = (blockIdx.x - b * (Wn / CPB)) * CPB;
    const int jw = x0 >> 5;

    const unsigned* __restrict__ src = g_bm_t + ((size_t)b * JW + jw) * Hn;
#pragma unroll
    for (int r = 0; r < 3; ++r)
        sh_t[t + NT * r] = src[t + NT * r];    // contiguous, L2-hot
    if (t < CPB * PAD) {
        const int c = t >> 3, o = t & 7;
        lines[c * LWP + o] = LARGE;
        lines[c * LWP + LWD - PAD + o] = LARGE;
    }
    __syncthreads();

    {   // row distances: thread owns y=t, CPB columns via funnels
        const int y = t;
        const unsigned wm1 = sh_t[y];
        const unsigned w0  = sh_t[Hn + y];
        const unsigned wp1 = sh_t[2 * Hn + y];
        const unsigned long long vr = ((unsigned long long)wp1 << 32) | w0;
        const unsigned long long vl = ((unsigned long long)w0 << 32) | wm1;
        const int bp0 = x0 & 31;
        const unsigned* __restrict__ gfb = g_bm_t + (size_t)b * JW * Hn;
#pragma unroll
        for (int xl = 0; xl < CPB; ++xl) {
            const int bp = bp0 + xl;           // <= 31
            const int xg = x0 + xl;
            int dr, dl;
            const unsigned long long r64 = vr >> bp;
            if (r64) {
                dr = __ffsll(r64) - 1;
            } else {                            // rare exact fallback
                dr = 0x7fff;
                for (int j = jw + 2; j < 12; ++j) {
                    const unsigned uu = gfb[(j + 1) * Hn + y];
                    if (uu) { dr = j * 32 - xg + __ffs(uu) - 1; break; }
                }
            }
            const unsigned long long l64 = vl << (31 - bp);
            if (l64) {
                dl = __clzll(l64);
            } else {
                dl = 0x7fff;
                for (int j = jw - 2; j >= 0; --j) {
                    const unsigned uu = gfb[(j + 1) * Hn + y];
                    if (uu) { dl = xg - j * 32 - 31 + __clz(uu); break; }
                }
            }
            const int d = min(dl, dr);
            lines[xl * LWP + PAD + y] = (d < 384) ? (float)(d * d) : LARGE;
        }
    }
    __syncthreads();

    // column search: 12 warps = 3 segments x 4 columns
    const int cl = w & 3, seg = w >> 2;
    const float* __restrict__ row = &lines[cl * LWP];
    const int ibase = seg * 128 + lane;

    float best[4];
#pragma unroll
    for (int gq = 0; gq < 4; gq += 2) {
        float a[2][9];
#pragma unroll
        for (int s = 0; s < 2; ++s) {
            const float* p = row + PAD + ibase + 32 * (gq + s);
            a[s][0] = p[0];
            a[s][1] = p[1];  a[s][2] = p[-1];
            a[s][3] = p[2];  a[s][4] = p[-2];
            a[s][5] = p[3];  a[s][6] = p[-3];
            a[s][7] = p[4];  a[s][8] = p[-4];
        }
#pragma unroll
        for (int s = 0; s < 2; ++s) {
            const float c1 = fminf(a[s][1], a[s][2]) + 1.0f;
            const float c2 = fminf(a[s][3], a[s][4]) + 4.0f;
            const float c3 = fminf(a[s][5], a[s][6]) + 9.0f;
            const float c4 = fminf(a[s][7], a[s][8]) + 16.0f;
            best[gq + s] = fminf(a[s][0], fminf(fminf(c1, c2), fminf(c3, c4)));
        }
    }
#pragma unroll
    for (int s = 0; s < 4; ++s)
        best[s] = near_far(row, best[s], ibase + 32 * s);

#pragma unroll
    for (int s = 0; s < 4; ++s)
        sh_o[(ibase + 32 * s) * 5 + cl] = sqrt_approx(best[s]);
    __syncthreads();

    const int c_st = t & 3, y_st = t >> 2;
    float* __restrict__ dst = out + ((size_t)b * Hn) * Wn + x0 + c_st;
#pragma unroll
    for (int r = 0; r < 4; ++r) {
        const int y = y_st + 96 * r;
        dst[(size_t)y * Wn] = sh_o[y * 5 + c_st];
    }
}

extern "C" void kernel_launch(void* const* d_in, const int* in_sizes, int n_in,
                              void* d_out, int out_size) {
    const float* mask = (const float*)d_in[0];
    float* out = (float*)d_out;
    (void)in_sizes; (void)n_in; (void)out_size;

    edt_all<<<GRID, NT>>>(mask, out);
}